// round 10
// baseline (speedup 1.0000x reference)
#include <cuda_runtime.h>
#include <cuda_bf16.h>
#include <cstdint>

#define Bv 4
#define Tv 2048
#define Cv 1024
#define Hv 16
#define HSv 64
#define MROWS (Bv * Tv)        // 8192
#define NQKV  (3 * Cv)         // 3072

// ------------------------- device scratch (no allocs) -----------------------
__device__ __nv_bfloat16 g_qkvh[(size_t)MROWS * NQKV]; // qkv split hi [8192,3072]
__device__ __nv_bfloat16 g_qkvl[(size_t)MROWS * NQKV];
__device__ __nv_bfloat16 g_xh[(size_t)MROWS * Cv];
__device__ __nv_bfloat16 g_xl[(size_t)MROWS * Cv];
__device__ __nv_bfloat16 g_yh[(size_t)MROWS * Cv];
__device__ __nv_bfloat16 g_yl[(size_t)MROWS * Cv];
__device__ __nv_bfloat16 g_wah[(size_t)NQKV * Cv];     // w_attn^T [3072,1024]
__device__ __nv_bfloat16 g_wal[(size_t)NQKV * Cv];
__device__ __nv_bfloat16 g_wph[(size_t)Cv * Cv];       // w_proj^T [1024,1024]
__device__ __nv_bfloat16 g_wpl[(size_t)Cv * Cv];

// ------------------------- PTX helpers (sm_103-base safe) --------------------
__device__ __forceinline__ uint32_t smem_u32(const void* p) {
    uint32_t a;
    asm("{ .reg .u64 t; cvta.to.shared.u64 t, %1; cvt.u32.u64 %0, t; }"
        : "=r"(a) : "l"(p));
    return a;
}
__device__ __forceinline__ void cp_async16(uint32_t dst, const void* src) {
    asm volatile("cp.async.cg.shared.global [%0], [%1], 16;"
                 :: "r"(dst), "l"(src) : "memory");
}
__device__ __forceinline__ void cp_commit() {
    asm volatile("cp.async.commit_group;" ::: "memory");
}
template <int N>
__device__ __forceinline__ void cp_wait() {
    asm volatile("cp.async.wait_group %0;" :: "n"(N) : "memory");
}
__device__ __forceinline__ void ldsm4(uint32_t* r, uint32_t addr) {
    asm volatile("ldmatrix.sync.aligned.m8n8.x4.shared.b16 {%0,%1,%2,%3}, [%4];"
                 : "=r"(r[0]), "=r"(r[1]), "=r"(r[2]), "=r"(r[3]) : "r"(addr));
}
__device__ __forceinline__ void ldsm4t(uint32_t* r, uint32_t addr) {
    asm volatile("ldmatrix.sync.aligned.m8n8.x4.trans.shared.b16 {%0,%1,%2,%3}, [%4];"
                 : "=r"(r[0]), "=r"(r[1]), "=r"(r[2]), "=r"(r[3]) : "r"(addr));
}
__device__ __forceinline__ void mma_bf16(float* c, const uint32_t* a,
                                         uint32_t b0, uint32_t b1) {
    asm volatile(
        "mma.sync.aligned.m16n8k16.row.col.f32.bf16.bf16.f32 "
        "{%0,%1,%2,%3}, {%4,%5,%6,%7}, {%8,%9}, {%0,%1,%2,%3};"
        : "+f"(c[0]), "+f"(c[1]), "+f"(c[2]), "+f"(c[3])
        : "r"(a[0]), "r"(a[1]), "r"(a[2]), "r"(a[3]), "r"(b0), "r"(b1));
}
// split two fp32 into packed bf16 hi-pair and lo-pair (elem0 in low half)
__device__ __forceinline__ void split_pack2(float v0, float v1,
                                            uint32_t& h, uint32_t& l) {
    __nv_bfloat16 h0 = __float2bfloat16(v0);
    __nv_bfloat16 h1 = __float2bfloat16(v1);
    __nv_bfloat16 l0 = __float2bfloat16(v0 - __bfloat162float(h0));
    __nv_bfloat16 l1 = __float2bfloat16(v1 - __bfloat162float(h1));
    __nv_bfloat162 hh(h0, h1), ll(l0, l1);
    h = *(uint32_t*)&hh;
    l = *(uint32_t*)&ll;
}

// ---------------------------------------------------------------------------
// Split fp32 -> (bf16 hi, bf16 lo)
// ---------------------------------------------------------------------------
__global__ void __launch_bounds__(256) split_kernel(
    const float* __restrict__ in, __nv_bfloat16* __restrict__ hi,
    __nv_bfloat16* __restrict__ lo, size_t n4)
{
    size_t i = (size_t)blockIdx.x * blockDim.x + threadIdx.x;
    size_t stride = (size_t)gridDim.x * blockDim.x;
    for (; i < n4; i += stride) {
        float4 v = ((const float4*)in)[i];
        uint32_t h01, l01, h23, l23;
        split_pack2(v.x, v.y, h01, l01);
        split_pack2(v.z, v.w, h23, l23);
        ((uint32_t*)hi)[i * 2 + 0] = h01;
        ((uint32_t*)hi)[i * 2 + 1] = h23;
        ((uint32_t*)lo)[i * 2 + 0] = l01;
        ((uint32_t*)lo)[i * 2 + 1] = l23;
    }
}

// ---------------------------------------------------------------------------
// Transpose + split: w [K,N] fp32 -> hiT/loT [N,K] bf16
// ---------------------------------------------------------------------------
__global__ void __launch_bounds__(256) splitT_kernel(
    const float* __restrict__ w, __nv_bfloat16* __restrict__ hiT,
    __nv_bfloat16* __restrict__ loT, int K, int N)
{
    __shared__ float t[32][33];
    int n0 = blockIdx.x * 32;
    int k0 = blockIdx.y * 32;
    int tx = threadIdx.x & 31;
    int ty = threadIdx.x >> 5;
#pragma unroll
    for (int i = 0; i < 4; i++)
        t[ty + i * 8][tx] = w[(size_t)(k0 + ty + i * 8) * N + n0 + tx];
    __syncthreads();
#pragma unroll
    for (int i = 0; i < 4; i++) {
        float v = t[tx][ty + i * 8];
        __nv_bfloat16 h = __float2bfloat16(v);
        __nv_bfloat16 l = __float2bfloat16(v - __bfloat162float(h));
        size_t o = (size_t)(n0 + ty + i * 8) * K + k0 + tx;
        hiT[o] = h;
        loT[o] = l;
    }
}

// ---------------------------------------------------------------------------
// HMMA split-bf16 GEMM. Pass-major MMA ordering: each accumulator is
// revisited only after 16 intervening MMAs (RAW chain spacing 2 -> 16).
// ---------------------------------------------------------------------------
#define PADB 80
#define PART_BYTES (128 * PADB)
#define STAGE_BYTES (4 * PART_BYTES)
#define GH_SMEM (2 * STAGE_BYTES)       // 81920

template <bool SPLIT>
__global__ void __launch_bounds__(256, 2) gemm_hmma_kernel(
    const __nv_bfloat16* __restrict__ Ah, const __nv_bfloat16* __restrict__ Al,
    const __nv_bfloat16* __restrict__ Bh, const __nv_bfloat16* __restrict__ Bl,
    float* __restrict__ C, __nv_bfloat16* __restrict__ Ch,
    __nv_bfloat16* __restrict__ Cl, int M, int N, int K)
{
    extern __shared__ char smem[];
    const uint32_t smem_base = smem_u32(smem);

    const int tid = threadIdx.x;
    const int wid = tid >> 5;
    const int lane = tid & 31;
    const int bm = blockIdx.y * 128;
    const int bn = blockIdx.x * 128;
    const int wm = (wid & 1) * 64;
    const int wn = (wid >> 1) * 32;

    float acc[4][4][4];
#pragma unroll
    for (int i = 0; i < 4; i++)
#pragma unroll
        for (int j = 0; j < 4; j++)
#pragma unroll
            for (int r = 0; r < 4; r++) acc[i][j][r] = 0.0f;

    const __nv_bfloat16* srcs[4] = {
        Ah + (size_t)bm * K, Al + (size_t)bm * K,
        Bh + (size_t)bn * K, Bl + (size_t)bn * K };

    const int nch = K >> 5;

    auto load_stage = [&](int kc) {
        const uint32_t sb = smem_base + (kc & 1) * STAGE_BYTES;
        const size_t koff = (size_t)kc << 5;
#pragma unroll
        for (int p = 0; p < 4; p++) {
#pragma unroll
            for (int r = 0; r < 2; r++) {
                int c = tid + r * 256;
                int row = c >> 2;
                int cn = c & 3;
                cp_async16(sb + p * PART_BYTES + row * PADB + cn * 16,
                           srcs[p] + (size_t)row * K + koff + cn * 8);
            }
        }
    };

    load_stage(0);
    cp_commit();

    const int arow_l = ((lane >> 3) & 1) * 8 + (lane & 7);
    const uint32_t acol_l = (uint32_t)((lane >> 4) * 16);
    const int brow_l = ((lane >> 4) << 3) + (lane & 7);
    const uint32_t bcol_l = (uint32_t)(((lane >> 3) & 1) * 16);

    for (int kc = 0; kc < nch; kc++) {
        if (kc + 1 < nch) {
            load_stage(kc + 1);
            cp_commit();
            cp_wait<1>();
        } else {
            cp_wait<0>();
        }
        __syncthreads();

        const uint32_t sb = smem_base + (kc & 1) * STAGE_BYTES;
        const uint32_t aH = sb, aL = sb + PART_BYTES;
        const uint32_t bH = sb + 2 * PART_BYTES, bL = sb + 3 * PART_BYTES;

#pragma unroll
        for (int s = 0; s < 2; s++) {
            uint32_t ah[4][4], al[4][4], bh[2][4], bl[2][4];
            const uint32_t ac = acol_l + s * 32;
            const uint32_t bc = bcol_l + s * 32;
#pragma unroll
            for (int i = 0; i < 4; i++) {
                uint32_t off = (uint32_t)((wm + i * 16 + arow_l) * PADB) + ac;
                ldsm4(ah[i], aH + off);
                ldsm4(al[i], aL + off);
            }
#pragma unroll
            for (int j = 0; j < 2; j++) {
                uint32_t off = (uint32_t)((wn + j * 16 + brow_l) * PADB) + bc;
                ldsm4(bh[j], bH + off);
                ldsm4(bl[j], bL + off);
            }
            // pass-major: all 16 acc tiles per pass (RAW spacing = 16)
#pragma unroll
            for (int i = 0; i < 4; i++)
#pragma unroll
                for (int j = 0; j < 2; j++) {
                    mma_bf16(acc[i][2 * j],     ah[i], bh[j][0], bh[j][1]);
                    mma_bf16(acc[i][2 * j + 1], ah[i], bh[j][2], bh[j][3]);
                }
#pragma unroll
            for (int i = 0; i < 4; i++)
#pragma unroll
                for (int j = 0; j < 2; j++) {
                    mma_bf16(acc[i][2 * j],     ah[i], bl[j][0], bl[j][1]);
                    mma_bf16(acc[i][2 * j + 1], ah[i], bl[j][2], bl[j][3]);
                }
#pragma unroll
            for (int i = 0; i < 4; i++)
#pragma unroll
                for (int j = 0; j < 2; j++) {
                    mma_bf16(acc[i][2 * j],     al[i], bh[j][0], bh[j][1]);
                    mma_bf16(acc[i][2 * j + 1], al[i], bh[j][2], bh[j][3]);
                }
        }
        __syncthreads();
    }

    const int erow = lane >> 2;
    const int ecol = (lane & 3) * 2;
#pragma unroll
    for (int i = 0; i < 4; i++) {
#pragma unroll
        for (int j = 0; j < 4; j++) {
            size_t r0 = (size_t)(bm + wm + i * 16 + erow);
            int c = bn + wn + j * 8 + ecol;
            if (SPLIT) {
                uint32_t h01, l01, h23, l23;
                split_pack2(acc[i][j][0], acc[i][j][1], h01, l01);
                split_pack2(acc[i][j][2], acc[i][j][3], h23, l23);
                ((uint32_t*)Ch)[(r0 * N + c) >> 1] = h01;
                ((uint32_t*)Cl)[(r0 * N + c) >> 1] = l01;
                ((uint32_t*)Ch)[((r0 + 8) * N + c) >> 1] = h23;
                ((uint32_t*)Cl)[((r0 + 8) * N + c) >> 1] = l23;
            } else {
                *(float2*)&C[r0 * N + c] = make_float2(acc[i][j][0], acc[i][j][1]);
                *(float2*)&C[(r0 + 8) * N + c] = make_float2(acc[i][j][2], acc[i][j][3]);
            }
        }
    }
}

// ---------------------------------------------------------------------------
// Tensor-core flash attention (causal), split-bf16 3-pass.
// S-loop: key-tile PAIRS with pass-major MMA order (RAW spacing 2 -> 4).
// PV-loop: d-tile PAIRS, pass-major (spacing 2 -> 4).
// ---------------------------------------------------------------------------
#define AT_RS 144                        // smem row stride bytes (128 data + 16)
#define AT_PART (128 * AT_RS)            // 18432
#define AT_QH 0
#define AT_QL AT_PART
#define AT_KV0 (2 * AT_PART)
#define AT_BUF (4 * AT_PART)
#define AT_SMEM (2 * AT_PART + 2 * AT_BUF)   // 184320

__global__ void __launch_bounds__(256) attn_tc_kernel(
    const __nv_bfloat16* __restrict__ qkvh,
    const __nv_bfloat16* __restrict__ qkvl,
    __nv_bfloat16* __restrict__ yh, __nv_bfloat16* __restrict__ yl)
{
    extern __shared__ char smem[];
    const uint32_t sb = smem_u32(smem);
    const int tid = threadIdx.x;
    const int wid = tid >> 5;
    const int lane = tid & 31;
    const int qb = (int)gridDim.x - 1 - (int)blockIdx.x;   // heavy CTAs first
    const int bh = blockIdx.y;
    const int b = bh >> 4;
    const int h = bh & 15;
    const int coff = h * HSv;

    // ---- Q tile cp.async (hi+lo) ----
    {
        const size_t qrow0 = (size_t)b * Tv + qb * 128;
        const __nv_bfloat16* s2[2] = { qkvh, qkvl };
#pragma unroll
        for (int p = 0; p < 2; p++)
#pragma unroll
            for (int i = 0; i < 4; i++) {
                int c = tid + i * 256;
                int row = c >> 3, cn = c & 7;
                cp_async16(sb + (p ? AT_QL : AT_QH) + row * AT_RS + cn * 16,
                           s2[p] + (qrow0 + row) * NQKV + coff + cn * 8);
            }
    }
    auto load_kv = [&](int kb) {
        const uint32_t base = sb + AT_KV0 + (kb & 1) * AT_BUF;
        const size_t krow0 = (size_t)b * Tv + kb * 128;
        const __nv_bfloat16* s4[4] = { qkvh + Cv, qkvl + Cv,
                                       qkvh + 2 * Cv, qkvl + 2 * Cv };
#pragma unroll
        for (int p = 0; p < 4; p++)
#pragma unroll
            for (int i = 0; i < 4; i++) {
                int c = tid + i * 256;
                int row = c >> 3, cn = c & 7;
                cp_async16(base + p * AT_PART + row * AT_RS + cn * 16,
                           s4[p] + (krow0 + row) * NQKV + coff + cn * 8);
            }
    };
    load_kv(0);
    cp_commit();
    cp_wait<0>();
    __syncthreads();

    // ---- Q fragments (cached for all kblocks) ----
    const int arow = ((lane >> 3) & 1) * 8 + (lane & 7);
    const uint32_t acol = (uint32_t)((lane >> 4) * 16);
    const int wq = wid * 16;
    uint32_t qh[4][4], ql[4][4];
#pragma unroll
    for (int t = 0; t < 4; t++) {
        uint32_t off = (uint32_t)((wq + arow) * AT_RS) + acol + t * 32;
        ldsm4(qh[t], sb + AT_QH + off);
        ldsm4(ql[t], sb + AT_QL + off);
    }

    const int brow = ((lane >> 4) << 3) + (lane & 7);
    const uint32_t bcol = (uint32_t)(((lane >> 3) & 1) * 16);
    const int vrow = (((lane >> 3) & 1) << 3) + (lane & 7);
    const uint32_t vcol = (uint32_t)((lane >> 4) * 16);

    float oacc[8][4];
#pragma unroll
    for (int e = 0; e < 8; e++)
#pragma unroll
        for (int r = 0; r < 4; r++) oacc[e][r] = 0.0f;
    float m0 = -1e30f, m1 = -1e30f, l0 = 0.0f, l1 = 0.0f;
    const int r0 = lane >> 2;
    const int cpair = (lane & 3) * 2;
    const int qi0 = qb * 128 + wq + r0;
    const int qi1 = qi0 + 8;

    for (int kb = 0; kb <= qb; kb++) {
        const bool have_next = (kb < qb);
        if (have_next) { load_kv(kb + 1); cp_commit(); }
        const uint32_t kvb = sb + AT_KV0 + (kb & 1) * AT_BUF;
        const uint32_t KH = kvb, KL = kvb + AT_PART;
        const uint32_t VH = kvb + 2 * AT_PART, VL = kvb + 3 * AT_PART;

        // ---- S = Q @ K^T (3-pass, key-tile pairs, pass-major) ----
        float sacc[16][4];
#pragma unroll
        for (int j = 0; j < 16; j++)
#pragma unroll
            for (int r = 0; r < 4; r++) sacc[j][r] = 0.0f;

#pragma unroll
        for (int gp = 0; gp < 4; gp++) {
            const int g0 = 2 * gp, g1 = 2 * gp + 1;
#pragma unroll
            for (int t = 0; t < 4; t++) {
                uint32_t kh0[4], kl0[4], kh1[4], kl1[4];
                uint32_t o0 = (uint32_t)((g0 * 16 + brow) * AT_RS) + bcol + t * 32;
                uint32_t o1 = (uint32_t)((g1 * 16 + brow) * AT_RS) + bcol + t * 32;
                ldsm4(kh0, KH + o0);
                ldsm4(kl0, KL + o0);
                ldsm4(kh1, KH + o1);
                ldsm4(kl1, KL + o1);
                // pass 0: qh * kh
                mma_bf16(sacc[2 * g0],     qh[t], kh0[0], kh0[1]);
                mma_bf16(sacc[2 * g0 + 1], qh[t], kh0[2], kh0[3]);
                mma_bf16(sacc[2 * g1],     qh[t], kh1[0], kh1[1]);
                mma_bf16(sacc[2 * g1 + 1], qh[t], kh1[2], kh1[3]);
                // pass 1: qh * kl
                mma_bf16(sacc[2 * g0],     qh[t], kl0[0], kl0[1]);
                mma_bf16(sacc[2 * g0 + 1], qh[t], kl0[2], kl0[3]);
                mma_bf16(sacc[2 * g1],     qh[t], kl1[0], kl1[1]);
                mma_bf16(sacc[2 * g1 + 1], qh[t], kl1[2], kl1[3]);
                // pass 2: ql * kh
                mma_bf16(sacc[2 * g0],     ql[t], kh0[0], kh0[1]);
                mma_bf16(sacc[2 * g0 + 1], ql[t], kh0[2], kh0[3]);
                mma_bf16(sacc[2 * g1],     ql[t], kh1[0], kh1[1]);
                mma_bf16(sacc[2 * g1 + 1], ql[t], kh1[2], kh1[3]);
            }
        }

        // ---- scale + causal mask + online softmax ----
        const bool diag = (kb == qb);
        float mx0 = -1e30f, mx1 = -1e30f;
#pragma unroll
        for (int j = 0; j < 16; j++) {
            int kj = kb * 128 + j * 8 + cpair;
            float v0 = sacc[j][0] * 0.125f, v1 = sacc[j][1] * 0.125f;
            float v2 = sacc[j][2] * 0.125f, v3 = sacc[j][3] * 0.125f;
            if (diag) {
                if (kj > qi0)     v0 = -1e30f;
                if (kj + 1 > qi0) v1 = -1e30f;
                if (kj > qi1)     v2 = -1e30f;
                if (kj + 1 > qi1) v3 = -1e30f;
            }
            sacc[j][0] = v0; sacc[j][1] = v1; sacc[j][2] = v2; sacc[j][3] = v3;
            mx0 = fmaxf(mx0, fmaxf(v0, v1));
            mx1 = fmaxf(mx1, fmaxf(v2, v3));
        }
        mx0 = fmaxf(mx0, __shfl_xor_sync(0xffffffffu, mx0, 1));
        mx0 = fmaxf(mx0, __shfl_xor_sync(0xffffffffu, mx0, 2));
        mx1 = fmaxf(mx1, __shfl_xor_sync(0xffffffffu, mx1, 1));
        mx1 = fmaxf(mx1, __shfl_xor_sync(0xffffffffu, mx1, 2));
        float mn0 = fmaxf(m0, mx0), mn1 = fmaxf(m1, mx1);
        float c0 = __expf(m0 - mn0), c1 = __expf(m1 - mn1);
        float rs0 = 0.0f, rs1 = 0.0f;
#pragma unroll
        for (int j = 0; j < 16; j++) {
            float p0 = __expf(sacc[j][0] - mn0);
            float p1 = __expf(sacc[j][1] - mn0);
            float p2 = __expf(sacc[j][2] - mn1);
            float p3 = __expf(sacc[j][3] - mn1);
            sacc[j][0] = p0; sacc[j][1] = p1; sacc[j][2] = p2; sacc[j][3] = p3;
            rs0 += p0 + p1;
            rs1 += p2 + p3;
        }
        rs0 += __shfl_xor_sync(0xffffffffu, rs0, 1);
        rs0 += __shfl_xor_sync(0xffffffffu, rs0, 2);
        rs1 += __shfl_xor_sync(0xffffffffu, rs1, 1);
        rs1 += __shfl_xor_sync(0xffffffffu, rs1, 2);
        l0 = l0 * c0 + rs0;
        l1 = l1 * c1 + rs1;
        m0 = mn0; m1 = mn1;
#pragma unroll
        for (int e = 0; e < 8; e++) {
            oacc[e][0] *= c0; oacc[e][1] *= c0;
            oacc[e][2] *= c1; oacc[e][3] *= c1;
        }

        // ---- O += P @ V (3-pass, d-tile pairs, pass-major) ----
#pragma unroll
        for (int kt = 0; kt < 8; kt++) {
            uint32_t ph[4], pl[4];
            split_pack2(sacc[2 * kt][0],     sacc[2 * kt][1],     ph[0], pl[0]);
            split_pack2(sacc[2 * kt][2],     sacc[2 * kt][3],     ph[1], pl[1]);
            split_pack2(sacc[2 * kt + 1][0], sacc[2 * kt + 1][1], ph[2], pl[2]);
            split_pack2(sacc[2 * kt + 1][2], sacc[2 * kt + 1][3], ph[3], pl[3]);
#pragma unroll
            for (int ep = 0; ep < 2; ep++) {
                const int e0 = 2 * ep, e1 = 2 * ep + 1;
                uint32_t vh0[4], vl0[4], vh1[4], vl1[4];
                uint32_t o0 = (uint32_t)((kt * 16 + vrow) * AT_RS) + vcol + e0 * 32;
                uint32_t o1 = (uint32_t)((kt * 16 + vrow) * AT_RS) + vcol + e1 * 32;
                ldsm4t(vh0, VH + o0);
                ldsm4t(vl0, VL + o0);
                ldsm4t(vh1, VH + o1);
                ldsm4t(vl1, VL + o1);
                // pass 0: ph * vh
                mma_bf16(oacc[2 * e0],     ph, vh0[0], vh0[1]);
                mma_bf16(oacc[2 * e0 + 1], ph, vh0[2], vh0[3]);
                mma_bf16(oacc[2 * e1],     ph, vh1[0], vh1[1]);
                mma_bf16(oacc[2 * e1 + 1], ph, vh1[2], vh1[3]);
                // pass 1: ph * vl
                mma_bf16(oacc[2 * e0],     ph, vl0[0], vl0[1]);
                mma_bf16(oacc[2 * e0 + 1], ph, vl0[2], vl0[3]);
                mma_bf16(oacc[2 * e1],     ph, vl1[0], vl1[1]);
                mma_bf16(oacc[2 * e1 + 1], ph, vl1[2], vl1[3]);
                // pass 2: pl * vh
                mma_bf16(oacc[2 * e0],     pl, vh0[0], vh0[1]);
                mma_bf16(oacc[2 * e0 + 1], pl, vh0[2], vh0[3]);
                mma_bf16(oacc[2 * e1],     pl, vh1[0], vh1[1]);
                mma_bf16(oacc[2 * e1 + 1], pl, vh1[2], vh1[3]);
            }
        }

        // drain the in-flight cp.async group (if any) before buffer reuse
        cp_wait<0>();
        __syncthreads();
    }

    // ---- epilogue: normalize, split, write yh/yl ----
    const float i0 = 1.0f / l0, i1 = 1.0f / l1;
    const size_t row0 = (size_t)b * Tv + qb * 128 + wq + r0;
#pragma unroll
    for (int e = 0; e < 8; e++) {
        uint32_t h01, l01, h23, l23;
        split_pack2(oacc[e][0] * i0, oacc[e][1] * i0, h01, l01);
        split_pack2(oacc[e][2] * i1, oacc[e][3] * i1, h23, l23);
        size_t o0 = (row0 * Cv + coff + e * 8 + cpair) >> 1;
        size_t o1 = ((row0 + 8) * Cv + coff + e * 8 + cpair) >> 1;
        ((uint32_t*)yh)[o0] = h01;
        ((uint32_t*)yl)[o0] = l01;
        ((uint32_t*)yh)[o1] = h23;
        ((uint32_t*)yl)[o1] = l23;
    }
}

// ---------------------------------------------------------------------------
extern "C" void kernel_launch(void* const* d_in, const int* in_sizes, int n_in,
                              void* d_out, int out_size)
{
    const float* x      = (const float*)d_in[0];   // [4,2048,1024]
    const float* w_attn = (const float*)d_in[1];   // [1024,3072]
    const float* w_proj = (const float*)d_in[2];   // [1024,1024]
    float* out = (float*)d_out;                    // [4,2048,1024]

    void *p_qh, *p_ql, *p_xh, *p_xl, *p_yh, *p_yl, *p_wah, *p_wal, *p_wph, *p_wpl;
    cudaGetSymbolAddress(&p_qh, g_qkvh);
    cudaGetSymbolAddress(&p_ql, g_qkvl);
    cudaGetSymbolAddress(&p_xh, g_xh);
    cudaGetSymbolAddress(&p_xl, g_xl);
    cudaGetSymbolAddress(&p_yh, g_yh);
    cudaGetSymbolAddress(&p_yl, g_yl);
    cudaGetSymbolAddress(&p_wah, g_wah);
    cudaGetSymbolAddress(&p_wal, g_wal);
    cudaGetSymbolAddress(&p_wph, g_wph);
    cudaGetSymbolAddress(&p_wpl, g_wpl);

    cudaFuncSetAttribute(gemm_hmma_kernel<true>,
                         cudaFuncAttributeMaxDynamicSharedMemorySize, GH_SMEM);
    cudaFuncSetAttribute(gemm_hmma_kernel<false>,
                         cudaFuncAttributeMaxDynamicSharedMemorySize, GH_SMEM);
    cudaFuncSetAttribute(attn_tc_kernel,
                         cudaFuncAttributeMaxDynamicSharedMemorySize, AT_SMEM);

    // 1. split x into bf16 hi/lo
    split_kernel<<<1024, 256>>>(x, (__nv_bfloat16*)p_xh, (__nv_bfloat16*)p_xl,
                                (size_t)MROWS * Cv / 4);
    // 2. transpose+split weights
    splitT_kernel<<<dim3(NQKV / 32, Cv / 32), 256>>>(
        w_attn, (__nv_bfloat16*)p_wah, (__nv_bfloat16*)p_wal, Cv, NQKV);
    splitT_kernel<<<dim3(Cv / 32, Cv / 32), 256>>>(
        w_proj, (__nv_bfloat16*)p_wph, (__nv_bfloat16*)p_wpl, Cv, Cv);

    // 3. qkv = x @ w_attn -> split bf16 outputs directly
    gemm_hmma_kernel<true><<<dim3(NQKV / 128, MROWS / 128), 256, GH_SMEM>>>(
        (const __nv_bfloat16*)p_xh, (const __nv_bfloat16*)p_xl,
        (const __nv_bfloat16*)p_wah, (const __nv_bfloat16*)p_wal,
        nullptr, (__nv_bfloat16*)p_qh, (__nv_bfloat16*)p_ql,
        MROWS, NQKV, Cv);

    // 4. tensor-core attention -> yh/yl
    attn_tc_kernel<<<dim3(Tv / 128, Bv * Hv), 256, AT_SMEM>>>(
        (const __nv_bfloat16*)p_qh, (const __nv_bfloat16*)p_ql,
        (__nv_bfloat16*)p_yh, (__nv_bfloat16*)p_yl);

    // 5. out = y @ w_proj (fp32 output)
    gemm_hmma_kernel<false><<<dim3(Cv / 128, MROWS / 128), 256, GH_SMEM>>>(
        (const __nv_bfloat16*)p_yh, (const __nv_bfloat16*)p_yl,
        (const __nv_bfloat16*)p_wph, (const __nv_bfloat16*)p_wpl,
        out, nullptr, nullptr, MROWS, Cv, Cv);
}

// round 11
// speedup vs baseline: 1.0365x; 1.0365x over previous
#include <cuda_runtime.h>
#include <cuda_bf16.h>
#include <cstdint>

#define Bv 4
#define Tv 2048
#define Cv 1024
#define Hv 16
#define HSv 64
#define MROWS (Bv * Tv)        // 8192
#define NQKV  (3 * Cv)         // 3072

// ------------------------- device scratch (no allocs) -----------------------
__device__ __nv_bfloat16 g_qkvh[(size_t)MROWS * NQKV]; // qkv split hi [8192,3072]
__device__ __nv_bfloat16 g_qkvl[(size_t)MROWS * NQKV];
__device__ __nv_bfloat16 g_xh[(size_t)MROWS * Cv];
__device__ __nv_bfloat16 g_xl[(size_t)MROWS * Cv];
__device__ __nv_bfloat16 g_yh[(size_t)MROWS * Cv];
__device__ __nv_bfloat16 g_yl[(size_t)MROWS * Cv];
__device__ __nv_bfloat16 g_wah[(size_t)NQKV * Cv];     // w_attn^T [3072,1024]
__device__ __nv_bfloat16 g_wal[(size_t)NQKV * Cv];
__device__ __nv_bfloat16 g_wph[(size_t)Cv * Cv];       // w_proj^T [1024,1024]
__device__ __nv_bfloat16 g_wpl[(size_t)Cv * Cv];

// ------------------------- PTX helpers (sm_103-base safe) --------------------
__device__ __forceinline__ uint32_t smem_u32(const void* p) {
    uint32_t a;
    asm("{ .reg .u64 t; cvta.to.shared.u64 t, %1; cvt.u32.u64 %0, t; }"
        : "=r"(a) : "l"(p));
    return a;
}
__device__ __forceinline__ void cp_async16(uint32_t dst, const void* src) {
    asm volatile("cp.async.cg.shared.global [%0], [%1], 16;"
                 :: "r"(dst), "l"(src) : "memory");
}
__device__ __forceinline__ void cp_commit() {
    asm volatile("cp.async.commit_group;" ::: "memory");
}
template <int N>
__device__ __forceinline__ void cp_wait() {
    asm volatile("cp.async.wait_group %0;" :: "n"(N) : "memory");
}
__device__ __forceinline__ void ldsm4(uint32_t* r, uint32_t addr) {
    asm volatile("ldmatrix.sync.aligned.m8n8.x4.shared.b16 {%0,%1,%2,%3}, [%4];"
                 : "=r"(r[0]), "=r"(r[1]), "=r"(r[2]), "=r"(r[3]) : "r"(addr));
}
__device__ __forceinline__ void ldsm4t(uint32_t* r, uint32_t addr) {
    asm volatile("ldmatrix.sync.aligned.m8n8.x4.trans.shared.b16 {%0,%1,%2,%3}, [%4];"
                 : "=r"(r[0]), "=r"(r[1]), "=r"(r[2]), "=r"(r[3]) : "r"(addr));
}
__device__ __forceinline__ void mma_bf16(float* c, const uint32_t* a,
                                         uint32_t b0, uint32_t b1) {
    asm volatile(
        "mma.sync.aligned.m16n8k16.row.col.f32.bf16.bf16.f32 "
        "{%0,%1,%2,%3}, {%4,%5,%6,%7}, {%8,%9}, {%0,%1,%2,%3};"
        : "+f"(c[0]), "+f"(c[1]), "+f"(c[2]), "+f"(c[3])
        : "r"(a[0]), "r"(a[1]), "r"(a[2]), "r"(a[3]), "r"(b0), "r"(b1));
}
// split two fp32 into packed bf16 hi-pair and lo-pair (elem0 in low half)
__device__ __forceinline__ void split_pack2(float v0, float v1,
                                            uint32_t& h, uint32_t& l) {
    __nv_bfloat16 h0 = __float2bfloat16(v0);
    __nv_bfloat16 h1 = __float2bfloat16(v1);
    __nv_bfloat16 l0 = __float2bfloat16(v0 - __bfloat162float(h0));
    __nv_bfloat16 l1 = __float2bfloat16(v1 - __bfloat162float(h1));
    __nv_bfloat162 hh(h0, h1), ll(l0, l1);
    h = *(uint32_t*)&hh;
    l = *(uint32_t*)&ll;
}

// ---------------------------------------------------------------------------
// Split fp32 -> (bf16 hi, bf16 lo)
// ---------------------------------------------------------------------------
__global__ void __launch_bounds__(256) split_kernel(
    const float* __restrict__ in, __nv_bfloat16* __restrict__ hi,
    __nv_bfloat16* __restrict__ lo, size_t n4)
{
    size_t i = (size_t)blockIdx.x * blockDim.x + threadIdx.x;
    size_t stride = (size_t)gridDim.x * blockDim.x;
    for (; i < n4; i += stride) {
        float4 v = ((const float4*)in)[i];
        uint32_t h01, l01, h23, l23;
        split_pack2(v.x, v.y, h01, l01);
        split_pack2(v.z, v.w, h23, l23);
        ((uint32_t*)hi)[i * 2 + 0] = h01;
        ((uint32_t*)hi)[i * 2 + 1] = h23;
        ((uint32_t*)lo)[i * 2 + 0] = l01;
        ((uint32_t*)lo)[i * 2 + 1] = l23;
    }
}

// ---------------------------------------------------------------------------
// Transpose + split: w [K,N] fp32 -> hiT/loT [N,K] bf16
// ---------------------------------------------------------------------------
__global__ void __launch_bounds__(256) splitT_kernel(
    const float* __restrict__ w, __nv_bfloat16* __restrict__ hiT,
    __nv_bfloat16* __restrict__ loT, int K, int N)
{
    __shared__ float t[32][33];
    int n0 = blockIdx.x * 32;
    int k0 = blockIdx.y * 32;
    int tx = threadIdx.x & 31;
    int ty = threadIdx.x >> 5;
#pragma unroll
    for (int i = 0; i < 4; i++)
        t[ty + i * 8][tx] = w[(size_t)(k0 + ty + i * 8) * N + n0 + tx];
    __syncthreads();
#pragma unroll
    for (int i = 0; i < 4; i++) {
        float v = t[tx][ty + i * 8];
        __nv_bfloat16 h = __float2bfloat16(v);
        __nv_bfloat16 l = __float2bfloat16(v - __bfloat162float(h));
        size_t o = (size_t)(n0 + ty + i * 8) * K + k0 + tx;
        hiT[o] = h;
        loT[o] = l;
    }
}

// ---------------------------------------------------------------------------
// HMMA split-bf16 GEMM, FAT-WARP config: 128x128 CTA tile, 128 threads,
// 4 warps in 2x2 grid, warp tile 64x64. LDSM:MMA ratio 0.167 (was 0.25),
// long per-warp MMA streams for ILP-based latency hiding. BK=32,
// double-buffered cp.async, 2 CTAs/SM (smem 2x80KB, regs <=252).
// ---------------------------------------------------------------------------
#define PADB 80
#define PART_BYTES (128 * PADB)
#define STAGE_BYTES (4 * PART_BYTES)
#define GH_SMEM (2 * STAGE_BYTES)       // 81920

template <bool SPLIT>
__global__ void __launch_bounds__(128, 2) gemm_hmma_kernel(
    const __nv_bfloat16* __restrict__ Ah, const __nv_bfloat16* __restrict__ Al,
    const __nv_bfloat16* __restrict__ Bh, const __nv_bfloat16* __restrict__ Bl,
    float* __restrict__ C, __nv_bfloat16* __restrict__ Ch,
    __nv_bfloat16* __restrict__ Cl, int M, int N, int K)
{
    extern __shared__ char smem[];
    const uint32_t smem_base = smem_u32(smem);

    const int tid = threadIdx.x;
    const int wid = tid >> 5;            // 0..3
    const int lane = tid & 31;
    const int bm = blockIdx.y * 128;
    const int bn = blockIdx.x * 128;
    const int wm = (wid >> 1) * 64;      // warp M offset (0 or 64)
    const int wn = (wid & 1) * 64;       // warp N offset (0 or 64)

    float acc[4][8][4];                  // 4 m16-tiles x 8 n8-tiles x 4
#pragma unroll
    for (int i = 0; i < 4; i++)
#pragma unroll
        for (int j = 0; j < 8; j++)
#pragma unroll
            for (int r = 0; r < 4; r++) acc[i][j][r] = 0.0f;

    const __nv_bfloat16* srcs[4] = {
        Ah + (size_t)bm * K, Al + (size_t)bm * K,
        Bh + (size_t)bn * K, Bl + (size_t)bn * K };

    const int nch = K >> 5;

    // loader: 2048 16B-chunks per stage / 128 threads = 16 per thread
    auto load_stage = [&](int kc) {
        const uint32_t sb = smem_base + (kc & 1) * STAGE_BYTES;
        const size_t koff = (size_t)kc << 5;
#pragma unroll
        for (int p = 0; p < 4; p++) {
#pragma unroll
            for (int r = 0; r < 4; r++) {
                int c = tid + r * 128;          // 0..511 within part
                int row = c >> 2;
                int cn = c & 3;
                cp_async16(sb + p * PART_BYTES + row * PADB + cn * 16,
                           srcs[p] + (size_t)row * K + koff + cn * 8);
            }
        }
    };

    load_stage(0);
    cp_commit();

    const int arow_l = ((lane >> 3) & 1) * 8 + (lane & 7);
    const uint32_t acol_l = (uint32_t)((lane >> 4) * 16);
    const int brow_l = ((lane >> 4) << 3) + (lane & 7);
    const uint32_t bcol_l = (uint32_t)(((lane >> 3) & 1) * 16);

    for (int kc = 0; kc < nch; kc++) {
        if (kc + 1 < nch) {
            load_stage(kc + 1);
            cp_commit();
            cp_wait<1>();
        } else {
            cp_wait<0>();
        }
        __syncthreads();

        const uint32_t sb = smem_base + (kc & 1) * STAGE_BYTES;
        const uint32_t aH = sb, aL = sb + PART_BYTES;
        const uint32_t bH = sb + 2 * PART_BYTES, bL = sb + 3 * PART_BYTES;

#pragma unroll
        for (int s = 0; s < 2; s++) {
            uint32_t ah[4][4], al[4][4], bh[4][4], bl[4][4];
            const uint32_t ac = acol_l + s * 32;
            const uint32_t bc = bcol_l + s * 32;
#pragma unroll
            for (int i = 0; i < 4; i++) {
                uint32_t off = (uint32_t)((wm + i * 16 + arow_l) * PADB) + ac;
                ldsm4(ah[i], aH + off);
                ldsm4(al[i], aL + off);
            }
#pragma unroll
            for (int j = 0; j < 4; j++) {
                uint32_t off = (uint32_t)((wn + j * 16 + brow_l) * PADB) + bc;
                ldsm4(bh[j], bH + off);
                ldsm4(bl[j], bL + off);
            }
            // pass 0: Ah * Bh  (32 MMAs)
#pragma unroll
            for (int i = 0; i < 4; i++)
#pragma unroll
                for (int j = 0; j < 4; j++) {
                    mma_bf16(acc[i][2 * j],     ah[i], bh[j][0], bh[j][1]);
                    mma_bf16(acc[i][2 * j + 1], ah[i], bh[j][2], bh[j][3]);
                }
            // pass 1: Ah * Bl
#pragma unroll
            for (int i = 0; i < 4; i++)
#pragma unroll
                for (int j = 0; j < 4; j++) {
                    mma_bf16(acc[i][2 * j],     ah[i], bl[j][0], bl[j][1]);
                    mma_bf16(acc[i][2 * j + 1], ah[i], bl[j][2], bl[j][3]);
                }
            // pass 2: Al * Bh
#pragma unroll
            for (int i = 0; i < 4; i++)
#pragma unroll
                for (int j = 0; j < 4; j++) {
                    mma_bf16(acc[i][2 * j],     al[i], bh[j][0], bh[j][1]);
                    mma_bf16(acc[i][2 * j + 1], al[i], bh[j][2], bh[j][3]);
                }
        }
        __syncthreads();
    }

    const int erow = lane >> 2;
    const int ecol = (lane & 3) * 2;
#pragma unroll
    for (int i = 0; i < 4; i++) {
#pragma unroll
        for (int j = 0; j < 8; j++) {
            size_t r0 = (size_t)(bm + wm + i * 16 + erow);
            int c = bn + wn + j * 8 + ecol;
            if (SPLIT) {
                uint32_t h01, l01, h23, l23;
                split_pack2(acc[i][j][0], acc[i][j][1], h01, l01);
                split_pack2(acc[i][j][2], acc[i][j][3], h23, l23);
                ((uint32_t*)Ch)[(r0 * N + c) >> 1] = h01;
                ((uint32_t*)Cl)[(r0 * N + c) >> 1] = l01;
                ((uint32_t*)Ch)[((r0 + 8) * N + c) >> 1] = h23;
                ((uint32_t*)Cl)[((r0 + 8) * N + c) >> 1] = l23;
            } else {
                *(float2*)&C[r0 * N + c] = make_float2(acc[i][j][0], acc[i][j][1]);
                *(float2*)&C[(r0 + 8) * N + c] = make_float2(acc[i][j][2], acc[i][j][3]);
            }
        }
    }
}

// ---------------------------------------------------------------------------
// Tensor-core flash attention (causal), split-bf16 3-pass — unchanged (R9).
// ---------------------------------------------------------------------------
#define AT_RS 144                        // smem row stride bytes (128 data + 16)
#define AT_PART (128 * AT_RS)            // 18432
#define AT_QH 0
#define AT_QL AT_PART
#define AT_KV0 (2 * AT_PART)
#define AT_BUF (4 * AT_PART)
#define AT_SMEM (2 * AT_PART + 2 * AT_BUF)   // 184320

__global__ void __launch_bounds__(256) attn_tc_kernel(
    const __nv_bfloat16* __restrict__ qkvh,
    const __nv_bfloat16* __restrict__ qkvl,
    __nv_bfloat16* __restrict__ yh, __nv_bfloat16* __restrict__ yl)
{
    extern __shared__ char smem[];
    const uint32_t sb = smem_u32(smem);
    const int tid = threadIdx.x;
    const int wid = tid >> 5;
    const int lane = tid & 31;
    const int qb = (int)gridDim.x - 1 - (int)blockIdx.x;   // heavy CTAs first
    const int bh = blockIdx.y;
    const int b = bh >> 4;
    const int h = bh & 15;
    const int coff = h * HSv;

    // ---- Q tile cp.async (hi+lo) ----
    {
        const size_t qrow0 = (size_t)b * Tv + qb * 128;
        const __nv_bfloat16* s2[2] = { qkvh, qkvl };
#pragma unroll
        for (int p = 0; p < 2; p++)
#pragma unroll
            for (int i = 0; i < 4; i++) {
                int c = tid + i * 256;
                int row = c >> 3, cn = c & 7;
                cp_async16(sb + (p ? AT_QL : AT_QH) + row * AT_RS + cn * 16,
                           s2[p] + (qrow0 + row) * NQKV + coff + cn * 8);
            }
    }
    auto load_kv = [&](int kb) {
        const uint32_t base = sb + AT_KV0 + (kb & 1) * AT_BUF;
        const size_t krow0 = (size_t)b * Tv + kb * 128;
        const __nv_bfloat16* s4[4] = { qkvh + Cv, qkvl + Cv,
                                       qkvh + 2 * Cv, qkvl + 2 * Cv };
#pragma unroll
        for (int p = 0; p < 4; p++)
#pragma unroll
            for (int i = 0; i < 4; i++) {
                int c = tid + i * 256;
                int row = c >> 3, cn = c & 7;
                cp_async16(base + p * AT_PART + row * AT_RS + cn * 16,
                           s4[p] + (krow0 + row) * NQKV + coff + cn * 8);
            }
    };
    load_kv(0);
    cp_commit();
    cp_wait<0>();
    __syncthreads();

    // ---- Q fragments (cached for all kblocks) ----
    const int arow = ((lane >> 3) & 1) * 8 + (lane & 7);
    const uint32_t acol = (uint32_t)((lane >> 4) * 16);
    const int wq = wid * 16;
    uint32_t qh[4][4], ql[4][4];
#pragma unroll
    for (int t = 0; t < 4; t++) {
        uint32_t off = (uint32_t)((wq + arow) * AT_RS) + acol + t * 32;
        ldsm4(qh[t], sb + AT_QH + off);
        ldsm4(ql[t], sb + AT_QL + off);
    }

    const int brow = ((lane >> 4) << 3) + (lane & 7);
    const uint32_t bcol = (uint32_t)(((lane >> 3) & 1) * 16);
    const int vrow = (((lane >> 3) & 1) << 3) + (lane & 7);
    const uint32_t vcol = (uint32_t)((lane >> 4) * 16);

    float oacc[8][4];
#pragma unroll
    for (int e = 0; e < 8; e++)
#pragma unroll
        for (int r = 0; r < 4; r++) oacc[e][r] = 0.0f;
    float m0 = -1e30f, m1 = -1e30f, l0 = 0.0f, l1 = 0.0f;
    const int r0 = lane >> 2;
    const int cpair = (lane & 3) * 2;
    const int qi0 = qb * 128 + wq + r0;
    const int qi1 = qi0 + 8;

    for (int kb = 0; kb <= qb; kb++) {
        const bool have_next = (kb < qb);
        if (have_next) { load_kv(kb + 1); cp_commit(); }
        const uint32_t kvb = sb + AT_KV0 + (kb & 1) * AT_BUF;
        const uint32_t KH = kvb, KL = kvb + AT_PART;
        const uint32_t VH = kvb + 2 * AT_PART, VL = kvb + 3 * AT_PART;

        // ---- S = Q @ K^T (3-pass, key-tile pairs, pass-major) ----
        float sacc[16][4];
#pragma unroll
        for (int j = 0; j < 16; j++)
#pragma unroll
            for (int r = 0; r < 4; r++) sacc[j][r] = 0.0f;

#pragma unroll
        for (int gp = 0; gp < 4; gp++) {
            const int g0 = 2 * gp, g1 = 2 * gp + 1;
#pragma unroll
            for (int t = 0; t < 4; t++) {
                uint32_t kh0[4], kl0[4], kh1[4], kl1[4];
                uint32_t o0 = (uint32_t)((g0 * 16 + brow) * AT_RS) + bcol + t * 32;
                uint32_t o1 = (uint32_t)((g1 * 16 + brow) * AT_RS) + bcol + t * 32;
                ldsm4(kh0, KH + o0);
                ldsm4(kl0, KL + o0);
                ldsm4(kh1, KH + o1);
                ldsm4(kl1, KL + o1);
                mma_bf16(sacc[2 * g0],     qh[t], kh0[0], kh0[1]);
                mma_bf16(sacc[2 * g0 + 1], qh[t], kh0[2], kh0[3]);
                mma_bf16(sacc[2 * g1],     qh[t], kh1[0], kh1[1]);
                mma_bf16(sacc[2 * g1 + 1], qh[t], kh1[2], kh1[3]);
                mma_bf16(sacc[2 * g0],     qh[t], kl0[0], kl0[1]);
                mma_bf16(sacc[2 * g0 + 1], qh[t], kl0[2], kl0[3]);
                mma_bf16(sacc[2 * g1],     qh[t], kl1[0], kl1[1]);
                mma_bf16(sacc[2 * g1 + 1], qh[t], kl1[2], kl1[3]);
                mma_bf16(sacc[2 * g0],     ql[t], kh0[0], kh0[1]);
                mma_bf16(sacc[2 * g0 + 1], ql[t], kh0[2], kh0[3]);
                mma_bf16(sacc[2 * g1],     ql[t], kh1[0], kh1[1]);
                mma_bf16(sacc[2 * g1 + 1], ql[t], kh1[2], kh1[3]);
            }
        }

        // ---- scale + causal mask + online softmax ----
        const bool diag = (kb == qb);
        float mx0 = -1e30f, mx1 = -1e30f;
#pragma unroll
        for (int j = 0; j < 16; j++) {
            int kj = kb * 128 + j * 8 + cpair;
            float v0 = sacc[j][0] * 0.125f, v1 = sacc[j][1] * 0.125f;
            float v2 = sacc[j][2] * 0.125f, v3 = sacc[j][3] * 0.125f;
            if (diag) {
                if (kj > qi0)     v0 = -1e30f;
                if (kj + 1 > qi0) v1 = -1e30f;
                if (kj > qi1)     v2 = -1e30f;
                if (kj + 1 > qi1) v3 = -1e30f;
            }
            sacc[j][0] = v0; sacc[j][1] = v1; sacc[j][2] = v2; sacc[j][3] = v3;
            mx0 = fmaxf(mx0, fmaxf(v0, v1));
            mx1 = fmaxf(mx1, fmaxf(v2, v3));
        }
        mx0 = fmaxf(mx0, __shfl_xor_sync(0xffffffffu, mx0, 1));
        mx0 = fmaxf(mx0, __shfl_xor_sync(0xffffffffu, mx0, 2));
        mx1 = fmaxf(mx1, __shfl_xor_sync(0xffffffffu, mx1, 1));
        mx1 = fmaxf(mx1, __shfl_xor_sync(0xffffffffu, mx1, 2));
        float mn0 = fmaxf(m0, mx0), mn1 = fmaxf(m1, mx1);
        float c0 = __expf(m0 - mn0), c1 = __expf(m1 - mn1);
        float rs0 = 0.0f, rs1 = 0.0f;
#pragma unroll
        for (int j = 0; j < 16; j++) {
            float p0 = __expf(sacc[j][0] - mn0);
            float p1 = __expf(sacc[j][1] - mn0);
            float p2 = __expf(sacc[j][2] - mn1);
            float p3 = __expf(sacc[j][3] - mn1);
            sacc[j][0] = p0; sacc[j][1] = p1; sacc[j][2] = p2; sacc[j][3] = p3;
            rs0 += p0 + p1;
            rs1 += p2 + p3;
        }
        rs0 += __shfl_xor_sync(0xffffffffu, rs0, 1);
        rs0 += __shfl_xor_sync(0xffffffffu, rs0, 2);
        rs1 += __shfl_xor_sync(0xffffffffu, rs1, 1);
        rs1 += __shfl_xor_sync(0xffffffffu, rs1, 2);
        l0 = l0 * c0 + rs0;
        l1 = l1 * c1 + rs1;
        m0 = mn0; m1 = mn1;
#pragma unroll
        for (int e = 0; e < 8; e++) {
            oacc[e][0] *= c0; oacc[e][1] *= c0;
            oacc[e][2] *= c1; oacc[e][3] *= c1;
        }

        // ---- O += P @ V (3-pass, d-tile pairs, pass-major) ----
#pragma unroll
        for (int kt = 0; kt < 8; kt++) {
            uint32_t ph[4], pl[4];
            split_pack2(sacc[2 * kt][0],     sacc[2 * kt][1],     ph[0], pl[0]);
            split_pack2(sacc[2 * kt][2],     sacc[2 * kt][3],     ph[1], pl[1]);
            split_pack2(sacc[2 * kt + 1][0], sacc[2 * kt + 1][1], ph[2], pl[2]);
            split_pack2(sacc[2 * kt + 1][2], sacc[2 * kt + 1][3], ph[3], pl[3]);
#pragma unroll
            for (int ep = 0; ep < 2; ep++) {
                const int e0 = 2 * ep, e1 = 2 * ep + 1;
                uint32_t vh0[4], vl0[4], vh1[4], vl1[4];
                uint32_t o0 = (uint32_t)((kt * 16 + vrow) * AT_RS) + vcol + e0 * 32;
                uint32_t o1 = (uint32_t)((kt * 16 + vrow) * AT_RS) + vcol + e1 * 32;
                ldsm4t(vh0, VH + o0);
                ldsm4t(vl0, VL + o0);
                ldsm4t(vh1, VH + o1);
                ldsm4t(vl1, VL + o1);
                mma_bf16(oacc[2 * e0],     ph, vh0[0], vh0[1]);
                mma_bf16(oacc[2 * e0 + 1], ph, vh0[2], vh0[3]);
                mma_bf16(oacc[2 * e1],     ph, vh1[0], vh1[1]);
                mma_bf16(oacc[2 * e1 + 1], ph, vh1[2], vh1[3]);
                mma_bf16(oacc[2 * e0],     ph, vl0[0], vl0[1]);
                mma_bf16(oacc[2 * e0 + 1], ph, vl0[2], vl0[3]);
                mma_bf16(oacc[2 * e1],     ph, vl1[0], vl1[1]);
                mma_bf16(oacc[2 * e1 + 1], ph, vl1[2], vl1[3]);
                mma_bf16(oacc[2 * e0],     pl, vh0[0], vh0[1]);
                mma_bf16(oacc[2 * e0 + 1], pl, vh0[2], vh0[3]);
                mma_bf16(oacc[2 * e1],     pl, vh1[0], vh1[1]);
                mma_bf16(oacc[2 * e1 + 1], pl, vh1[2], vh1[3]);
            }
        }

        // drain the in-flight cp.async group (if any) before buffer reuse
        cp_wait<0>();
        __syncthreads();
    }

    // ---- epilogue: normalize, split, write yh/yl ----
    const float i0 = 1.0f / l0, i1 = 1.0f / l1;
    const size_t row0 = (size_t)b * Tv + qb * 128 + wq + r0;
#pragma unroll
    for (int e = 0; e < 8; e++) {
        uint32_t h01, l01, h23, l23;
        split_pack2(oacc[e][0] * i0, oacc[e][1] * i0, h01, l01);
        split_pack2(oacc[e][2] * i1, oacc[e][3] * i1, h23, l23);
        size_t o0 = (row0 * Cv + coff + e * 8 + cpair) >> 1;
        size_t o1 = ((row0 + 8) * Cv + coff + e * 8 + cpair) >> 1;
        ((uint32_t*)yh)[o0] = h01;
        ((uint32_t*)yl)[o0] = l01;
        ((uint32_t*)yh)[o1] = h23;
        ((uint32_t*)yl)[o1] = l23;
    }
}

// ---------------------------------------------------------------------------
extern "C" void kernel_launch(void* const* d_in, const int* in_sizes, int n_in,
                              void* d_out, int out_size)
{
    const float* x      = (const float*)d_in[0];   // [4,2048,1024]
    const float* w_attn = (const float*)d_in[1];   // [1024,3072]
    const float* w_proj = (const float*)d_in[2];   // [1024,1024]
    float* out = (float*)d_out;                    // [4,2048,1024]

    void *p_qh, *p_ql, *p_xh, *p_xl, *p_yh, *p_yl, *p_wah, *p_wal, *p_wph, *p_wpl;
    cudaGetSymbolAddress(&p_qh, g_qkvh);
    cudaGetSymbolAddress(&p_ql, g_qkvl);
    cudaGetSymbolAddress(&p_xh, g_xh);
    cudaGetSymbolAddress(&p_xl, g_xl);
    cudaGetSymbolAddress(&p_yh, g_yh);
    cudaGetSymbolAddress(&p_yl, g_yl);
    cudaGetSymbolAddress(&p_wah, g_wah);
    cudaGetSymbolAddress(&p_wal, g_wal);
    cudaGetSymbolAddress(&p_wph, g_wph);
    cudaGetSymbolAddress(&p_wpl, g_wpl);

    cudaFuncSetAttribute(gemm_hmma_kernel<true>,
                         cudaFuncAttributeMaxDynamicSharedMemorySize, GH_SMEM);
    cudaFuncSetAttribute(gemm_hmma_kernel<false>,
                         cudaFuncAttributeMaxDynamicSharedMemorySize, GH_SMEM);
    cudaFuncSetAttribute(attn_tc_kernel,
                         cudaFuncAttributeMaxDynamicSharedMemorySize, AT_SMEM);

    // 1. split x into bf16 hi/lo
    split_kernel<<<1024, 256>>>(x, (__nv_bfloat16*)p_xh, (__nv_bfloat16*)p_xl,
                                (size_t)MROWS * Cv / 4);
    // 2. transpose+split weights
    splitT_kernel<<<dim3(NQKV / 32, Cv / 32), 256>>>(
        w_attn, (__nv_bfloat16*)p_wah, (__nv_bfloat16*)p_wal, Cv, NQKV);
    splitT_kernel<<<dim3(Cv / 32, Cv / 32), 256>>>(
        w_proj, (__nv_bfloat16*)p_wph, (__nv_bfloat16*)p_wpl, Cv, Cv);

    // 3. qkv = x @ w_attn -> split bf16 outputs directly
    gemm_hmma_kernel<true><<<dim3(NQKV / 128, MROWS / 128), 128, GH_SMEM>>>(
        (const __nv_bfloat16*)p_xh, (const __nv_bfloat16*)p_xl,
        (const __nv_bfloat16*)p_wah, (const __nv_bfloat16*)p_wal,
        nullptr, (__nv_bfloat16*)p_qh, (__nv_bfloat16*)p_ql,
        MROWS, NQKV, Cv);

    // 4. tensor-core attention -> yh/yl
    attn_tc_kernel<<<dim3(Tv / 128, Bv * Hv), 256, AT_SMEM>>>(
        (const __nv_bfloat16*)p_qh, (const __nv_bfloat16*)p_ql,
        (__nv_bfloat16*)p_yh, (__nv_bfloat16*)p_yl);

    // 5. out = y @ w_proj (fp32 output)
    gemm_hmma_kernel<false><<<dim3(Cv / 128, MROWS / 128), 128, GH_SMEM>>>(
        (const __nv_bfloat16*)p_yh, (const __nv_bfloat16*)p_yl,
        (const __nv_bfloat16*)p_wph, (const __nv_bfloat16*)p_wpl,
        out, nullptr, nullptr, MROWS, Cv, Cv);
}

// round 15
// speedup vs baseline: 1.0713x; 1.0336x over previous
#include <cuda_runtime.h>
#include <cuda_bf16.h>
#include <cstdint>

#define Bv 4
#define Tv 2048
#define Cv 1024
#define Hv 16
#define HSv 64
#define MROWS (Bv * Tv)        // 8192
#define NQKV  (3 * Cv)         // 3072

// ------------------------- device scratch (no allocs) -----------------------
__device__ __nv_bfloat16 g_qkvh[(size_t)MROWS * NQKV]; // qkv split hi [8192,3072]
__device__ __nv_bfloat16 g_qkvl[(size_t)MROWS * NQKV];
__device__ __nv_bfloat16 g_xh[(size_t)MROWS * Cv];
__device__ __nv_bfloat16 g_xl[(size_t)MROWS * Cv];
__device__ __nv_bfloat16 g_yh[(size_t)MROWS * Cv];
__device__ __nv_bfloat16 g_yl[(size_t)MROWS * Cv];
__device__ __nv_bfloat16 g_wah[(size_t)NQKV * Cv];     // w_attn^T [3072,1024]
__device__ __nv_bfloat16 g_wal[(size_t)NQKV * Cv];
__device__ __nv_bfloat16 g_wph[(size_t)Cv * Cv];       // w_proj^T [1024,1024]
__device__ __nv_bfloat16 g_wpl[(size_t)Cv * Cv];

// ------------------------- PTX helpers (sm_103-base safe) --------------------
__device__ __forceinline__ uint32_t smem_u32(const void* p) {
    uint32_t a;
    asm("{ .reg .u64 t; cvta.to.shared.u64 t, %1; cvt.u32.u64 %0, t; }"
        : "=r"(a) : "l"(p));
    return a;
}
__device__ __forceinline__ void cp_async16(uint32_t dst, const void* src) {
    asm volatile("cp.async.cg.shared.global [%0], [%1], 16;"
                 :: "r"(dst), "l"(src) : "memory");
}
__device__ __forceinline__ void cp_commit() {
    asm volatile("cp.async.commit_group;" ::: "memory");
}
template <int N>
__device__ __forceinline__ void cp_wait() {
    asm volatile("cp.async.wait_group %0;" :: "n"(N) : "memory");
}
__device__ __forceinline__ void ldsm4(uint32_t* r, uint32_t addr) {
    asm volatile("ldmatrix.sync.aligned.m8n8.x4.shared.b16 {%0,%1,%2,%3}, [%4];"
                 : "=r"(r[0]), "=r"(r[1]), "=r"(r[2]), "=r"(r[3]) : "r"(addr));
}
__device__ __forceinline__ void ldsm4t(uint32_t* r, uint32_t addr) {
    asm volatile("ldmatrix.sync.aligned.m8n8.x4.trans.shared.b16 {%0,%1,%2,%3}, [%4];"
                 : "=r"(r[0]), "=r"(r[1]), "=r"(r[2]), "=r"(r[3]) : "r"(addr));
}
__device__ __forceinline__ void mma_bf16(float* c, const uint32_t* a,
                                         uint32_t b0, uint32_t b1) {
    asm volatile(
        "mma.sync.aligned.m16n8k16.row.col.f32.bf16.bf16.f32 "
        "{%0,%1,%2,%3}, {%4,%5,%6,%7}, {%8,%9}, {%0,%1,%2,%3};"
        : "+f"(c[0]), "+f"(c[1]), "+f"(c[2]), "+f"(c[3])
        : "r"(a[0]), "r"(a[1]), "r"(a[2]), "r"(a[3]), "r"(b0), "r"(b1));
}
// split two fp32 into packed bf16 hi-pair and lo-pair (elem0 in low half)
__device__ __forceinline__ void split_pack2(float v0, float v1,
                                            uint32_t& h, uint32_t& l) {
    __nv_bfloat16 h0 = __float2bfloat16(v0);
    __nv_bfloat16 h1 = __float2bfloat16(v1);
    __nv_bfloat16 l0 = __float2bfloat16(v0 - __bfloat162float(h0));
    __nv_bfloat16 l1 = __float2bfloat16(v1 - __bfloat162float(h1));
    __nv_bfloat162 hh(h0, h1), ll(l0, l1);
    h = *(uint32_t*)&hh;
    l = *(uint32_t*)&ll;
}

// ---------------------------------------------------------------------------
// Split fp32 -> (bf16 hi, bf16 lo)
// ---------------------------------------------------------------------------
__global__ void __launch_bounds__(256) split_kernel(
    const float* __restrict__ in, __nv_bfloat16* __restrict__ hi,
    __nv_bfloat16* __restrict__ lo, size_t n4)
{
    size_t i = (size_t)blockIdx.x * blockDim.x + threadIdx.x;
    size_t stride = (size_t)gridDim.x * blockDim.x;
    for (; i < n4; i += stride) {
        float4 v = ((const float4*)in)[i];
        uint32_t h01, l01, h23, l23;
        split_pack2(v.x, v.y, h01, l01);
        split_pack2(v.z, v.w, h23, l23);
        ((uint32_t*)hi)[i * 2 + 0] = h01;
        ((uint32_t*)hi)[i * 2 + 1] = h23;
        ((uint32_t*)lo)[i * 2 + 0] = l01;
        ((uint32_t*)lo)[i * 2 + 1] = l23;
    }
}

// ---------------------------------------------------------------------------
// Transpose + split: w [K,N] fp32 -> hiT/loT [N,K] bf16
// ---------------------------------------------------------------------------
__global__ void __launch_bounds__(256) splitT_kernel(
    const float* __restrict__ w, __nv_bfloat16* __restrict__ hiT,
    __nv_bfloat16* __restrict__ loT, int K, int N)
{
    __shared__ float t[32][33];
    int n0 = blockIdx.x * 32;
    int k0 = blockIdx.y * 32;
    int tx = threadIdx.x & 31;
    int ty = threadIdx.x >> 5;
#pragma unroll
    for (int i = 0; i < 4; i++)
        t[ty + i * 8][tx] = w[(size_t)(k0 + ty + i * 8) * N + n0 + tx];
    __syncthreads();
#pragma unroll
    for (int i = 0; i < 4; i++) {
        float v = t[tx][ty + i * 8];
        __nv_bfloat16 h = __float2bfloat16(v);
        __nv_bfloat16 l = __float2bfloat16(v - __bfloat162float(h));
        size_t o = (size_t)(n0 + ty + i * 8) * K + k0 + tx;
        hiT[o] = h;
        loT[o] = l;
    }
}

// ---------------------------------------------------------------------------
// HMMA split-bf16 GEMM, FAT-WARP config (unchanged from R11, best measured):
// 128x128 CTA tile, 128 threads, 4 warps 2x2, warp tile 64x64, BK=32,
// double-buffered cp.async, 2 CTAs/SM.
// ---------------------------------------------------------------------------
#define PADB 80
#define PART_BYTES (128 * PADB)
#define STAGE_BYTES (4 * PART_BYTES)
#define GH_SMEM (2 * STAGE_BYTES)       // 81920

template <bool SPLIT>
__global__ void __launch_bounds__(128, 2) gemm_hmma_kernel(
    const __nv_bfloat16* __restrict__ Ah, const __nv_bfloat16* __restrict__ Al,
    const __nv_bfloat16* __restrict__ Bh, const __nv_bfloat16* __restrict__ Bl,
    float* __restrict__ C, __nv_bfloat16* __restrict__ Ch,
    __nv_bfloat16* __restrict__ Cl, int M, int N, int K)
{
    extern __shared__ char smem[];
    const uint32_t smem_base = smem_u32(smem);

    const int tid = threadIdx.x;
    const int wid = tid >> 5;            // 0..3
    const int lane = tid & 31;
    const int bm = blockIdx.y * 128;
    const int bn = blockIdx.x * 128;
    const int wm = (wid >> 1) * 64;
    const int wn = (wid & 1) * 64;

    float acc[4][8][4];
#pragma unroll
    for (int i = 0; i < 4; i++)
#pragma unroll
        for (int j = 0; j < 8; j++)
#pragma unroll
            for (int r = 0; r < 4; r++) acc[i][j][r] = 0.0f;

    const __nv_bfloat16* srcs[4] = {
        Ah + (size_t)bm * K, Al + (size_t)bm * K,
        Bh + (size_t)bn * K, Bl + (size_t)bn * K };

    const int nch = K >> 5;

    auto load_stage = [&](int kc) {
        const uint32_t sb = smem_base + (kc & 1) * STAGE_BYTES;
        const size_t koff = (size_t)kc << 5;
#pragma unroll
        for (int p = 0; p < 4; p++) {
#pragma unroll
            for (int r = 0; r < 4; r++) {
                int c = tid + r * 128;
                int row = c >> 2;
                int cn = c & 3;
                cp_async16(sb + p * PART_BYTES + row * PADB + cn * 16,
                           srcs[p] + (size_t)row * K + koff + cn * 8);
            }
        }
    };

    load_stage(0);
    cp_commit();

    const int arow_l = ((lane >> 3) & 1) * 8 + (lane & 7);
    const uint32_t acol_l = (uint32_t)((lane >> 4) * 16);
    const int brow_l = ((lane >> 4) << 3) + (lane & 7);
    const uint32_t bcol_l = (uint32_t)(((lane >> 3) & 1) * 16);

    for (int kc = 0; kc < nch; kc++) {
        if (kc + 1 < nch) {
            load_stage(kc + 1);
            cp_commit();
            cp_wait<1>();
        } else {
            cp_wait<0>();
        }
        __syncthreads();

        const uint32_t sb = smem_base + (kc & 1) * STAGE_BYTES;
        const uint32_t aH = sb, aL = sb + PART_BYTES;
        const uint32_t bH = sb + 2 * PART_BYTES, bL = sb + 3 * PART_BYTES;

#pragma unroll
        for (int s = 0; s < 2; s++) {
            uint32_t ah[4][4], al[4][4], bh[4][4], bl[4][4];
            const uint32_t ac = acol_l + s * 32;
            const uint32_t bc = bcol_l + s * 32;
#pragma unroll
            for (int i = 0; i < 4; i++) {
                uint32_t off = (uint32_t)((wm + i * 16 + arow_l) * PADB) + ac;
                ldsm4(ah[i], aH + off);
                ldsm4(al[i], aL + off);
            }
#pragma unroll
            for (int j = 0; j < 4; j++) {
                uint32_t off = (uint32_t)((wn + j * 16 + brow_l) * PADB) + bc;
                ldsm4(bh[j], bH + off);
                ldsm4(bl[j], bL + off);
            }
#pragma unroll
            for (int i = 0; i < 4; i++)
#pragma unroll
                for (int j = 0; j < 4; j++) {
                    mma_bf16(acc[i][2 * j],     ah[i], bh[j][0], bh[j][1]);
                    mma_bf16(acc[i][2 * j + 1], ah[i], bh[j][2], bh[j][3]);
                }
#pragma unroll
            for (int i = 0; i < 4; i++)
#pragma unroll
                for (int j = 0; j < 4; j++) {
                    mma_bf16(acc[i][2 * j],     ah[i], bl[j][0], bl[j][1]);
                    mma_bf16(acc[i][2 * j + 1], ah[i], bl[j][2], bl[j][3]);
                }
#pragma unroll
            for (int i = 0; i < 4; i++)
#pragma unroll
                for (int j = 0; j < 4; j++) {
                    mma_bf16(acc[i][2 * j],     al[i], bh[j][0], bh[j][1]);
                    mma_bf16(acc[i][2 * j + 1], al[i], bh[j][2], bh[j][3]);
                }
        }
        __syncthreads();
    }

    const int erow = lane >> 2;
    const int ecol = (lane & 3) * 2;
#pragma unroll
    for (int i = 0; i < 4; i++) {
#pragma unroll
        for (int j = 0; j < 8; j++) {
            size_t r0 = (size_t)(bm + wm + i * 16 + erow);
            int c = bn + wn + j * 8 + ecol;
            if (SPLIT) {
                uint32_t h01, l01, h23, l23;
                split_pack2(acc[i][j][0], acc[i][j][1], h01, l01);
                split_pack2(acc[i][j][2], acc[i][j][3], h23, l23);
                ((uint32_t*)Ch)[(r0 * N + c) >> 1] = h01;
                ((uint32_t*)Cl)[(r0 * N + c) >> 1] = l01;
                ((uint32_t*)Ch)[((r0 + 8) * N + c) >> 1] = h23;
                ((uint32_t*)Cl)[((r0 + 8) * N + c) >> 1] = l23;
            } else {
                *(float2*)&C[r0 * N + c] = make_float2(acc[i][j][0], acc[i][j][1]);
                *(float2*)&C[(r0 + 8) * N + c] = make_float2(acc[i][j][2], acc[i][j][3]);
            }
        }
    }
}

// ---------------------------------------------------------------------------
// Tensor-core flash attention v2: Q-block 64, K-block 64, 128 threads
// (4 warps x 16 q-rows), smem 92160 B -> 2 CTAs/SM so softmax of one CTA
// overlaps MMAs of the other. Split-bf16 3-pass numerics unchanged.
// exp in base-2 domain (scale folds in log2e).
// ---------------------------------------------------------------------------
#define A2_RS 144                        // 128B data + 16 pad
#define A2_PART (64 * A2_RS)             // 9216
#define A2_QH 0
#define A2_QL A2_PART
#define A2_KV0 (2 * A2_PART)
#define A2_BUF (4 * A2_PART)             // 36864
#define A2_SMEM (2 * A2_PART + 2 * A2_BUF)   // 92160

__global__ void __launch_bounds__(128) attn_tc_kernel(
    const __nv_bfloat16* __restrict__ qkvh,
    const __nv_bfloat16* __restrict__ qkvl,
    __nv_bfloat16* __restrict__ yh, __nv_bfloat16* __restrict__ yl)
{
    extern __shared__ char smem[];
    const uint32_t sb = smem_u32(smem);
    const int tid = threadIdx.x;
    const int wid = tid >> 5;            // 0..3
    const int lane = tid & 31;
    const int qb = (int)gridDim.x - 1 - (int)blockIdx.x;   // heavy CTAs first
    const int bh = blockIdx.y;
    const int b = bh >> 4;
    const int h = bh & 15;
    const int coff = h * HSv;
    const float SC = 0.125f * 1.44269504f;   // scale * log2(e)

    // ---- Q tile cp.async (hi+lo): 64 rows ----
    {
        const size_t qrow0 = (size_t)b * Tv + qb * 64;
        const __nv_bfloat16* s2[2] = { qkvh, qkvl };
#pragma unroll
        for (int p = 0; p < 2; p++)
#pragma unroll
            for (int i = 0; i < 4; i++) {
                int c = tid + i * 128;          // 0..511
                int row = c >> 3, cn = c & 7;
                cp_async16(sb + (p ? A2_QL : A2_QH) + row * A2_RS + cn * 16,
                           s2[p] + (qrow0 + row) * NQKV + coff + cn * 8);
            }
    }
    auto load_kv = [&](int kb) {
        const uint32_t base = sb + A2_KV0 + (kb & 1) * A2_BUF;
        const size_t krow0 = (size_t)b * Tv + kb * 64;
        const __nv_bfloat16* s4[4] = { qkvh + Cv, qkvl + Cv,
                                       qkvh + 2 * Cv, qkvl + 2 * Cv };
#pragma unroll
        for (int p = 0; p < 4; p++)
#pragma unroll
            for (int i = 0; i < 4; i++) {
                int c = tid + i * 128;
                int row = c >> 3, cn = c & 7;
                cp_async16(base + p * A2_PART + row * A2_RS + cn * 16,
                           s4[p] + (krow0 + row) * NQKV + coff + cn * 8);
            }
    };
    load_kv(0);
    cp_commit();
    cp_wait<0>();
    __syncthreads();

    // ---- Q fragments (cached for all kblocks) ----
    const int arow = ((lane >> 3) & 1) * 8 + (lane & 7);
    const uint32_t acol = (uint32_t)((lane >> 4) * 16);
    const int wq = wid * 16;
    uint32_t qh[4][4], ql[4][4];
#pragma unroll
    for (int t = 0; t < 4; t++) {
        uint32_t off = (uint32_t)((wq + arow) * A2_RS) + acol + t * 32;
        ldsm4(qh[t], sb + A2_QH + off);
        ldsm4(ql[t], sb + A2_QL + off);
    }

    const int brow = ((lane >> 4) << 3) + (lane & 7);
    const uint32_t bcol = (uint32_t)(((lane >> 3) & 1) * 16);
    const int vrow = (((lane >> 3) & 1) << 3) + (lane & 7);
    const uint32_t vcol = (uint32_t)((lane >> 4) * 16);

    float oacc[8][4];
#pragma unroll
    for (int e = 0; e < 8; e++)
#pragma unroll
        for (int r = 0; r < 4; r++) oacc[e][r] = 0.0f;
    float m0 = -1e30f, m1 = -1e30f, l0 = 0.0f, l1 = 0.0f;
    const int r0 = lane >> 2;
    const int cpair = (lane & 3) * 2;
    const int qi0 = qb * 64 + wq + r0;
    const int qi1 = qi0 + 8;

    for (int kb = 0; kb <= qb; kb++) {
        if (kb < qb) { load_kv(kb + 1); cp_commit(); }
        const uint32_t kvb = sb + A2_KV0 + (kb & 1) * A2_BUF;
        const uint32_t KH = kvb, KL = kvb + A2_PART;
        const uint32_t VH = kvb + 2 * A2_PART, VL = kvb + 3 * A2_PART;

        // ---- S = Q @ K^T (3-pass, key-tile pairs, pass-major) ----
        float sacc[8][4];
#pragma unroll
        for (int j = 0; j < 8; j++)
#pragma unroll
            for (int r = 0; r < 4; r++) sacc[j][r] = 0.0f;

#pragma unroll
        for (int gp = 0; gp < 2; gp++) {
            const int g0 = 2 * gp, g1 = 2 * gp + 1;
#pragma unroll
            for (int t = 0; t < 4; t++) {
                uint32_t kh0[4], kl0[4], kh1[4], kl1[4];
                uint32_t o0 = (uint32_t)((g0 * 16 + brow) * A2_RS) + bcol + t * 32;
                uint32_t o1 = (uint32_t)((g1 * 16 + brow) * A2_RS) + bcol + t * 32;
                ldsm4(kh0, KH + o0);
                ldsm4(kl0, KL + o0);
                ldsm4(kh1, KH + o1);
                ldsm4(kl1, KL + o1);
                mma_bf16(sacc[2 * g0],     qh[t], kh0[0], kh0[1]);
                mma_bf16(sacc[2 * g0 + 1], qh[t], kh0[2], kh0[3]);
                mma_bf16(sacc[2 * g1],     qh[t], kh1[0], kh1[1]);
                mma_bf16(sacc[2 * g1 + 1], qh[t], kh1[2], kh1[3]);
                mma_bf16(sacc[2 * g0],     qh[t], kl0[0], kl0[1]);
                mma_bf16(sacc[2 * g0 + 1], qh[t], kl0[2], kl0[3]);
                mma_bf16(sacc[2 * g1],     qh[t], kl1[0], kl1[1]);
                mma_bf16(sacc[2 * g1 + 1], qh[t], kl1[2], kl1[3]);
                mma_bf16(sacc[2 * g0],     ql[t], kh0[0], kh0[1]);
                mma_bf16(sacc[2 * g0 + 1], ql[t], kh0[2], kh0[3]);
                mma_bf16(sacc[2 * g1],     ql[t], kh1[0], kh1[1]);
                mma_bf16(sacc[2 * g1 + 1], ql[t], kh1[2], kh1[3]);
            }
        }

        // ---- scale(log2 domain) + causal mask + online softmax ----
        const bool diag = (kb == qb);
        float mx0 = -1e30f, mx1 = -1e30f;
#pragma unroll
        for (int j = 0; j < 8; j++) {
            int kj = kb * 64 + j * 8 + cpair;
            float v0 = sacc[j][0] * SC, v1 = sacc[j][1] * SC;
            float v2 = sacc[j][2] * SC, v3 = sacc[j][3] * SC;
            if (diag) {
                if (kj > qi0)     v0 = -1e30f;
                if (kj + 1 > qi0) v1 = -1e30f;
                if (kj > qi1)     v2 = -1e30f;
                if (kj + 1 > qi1) v3 = -1e30f;
            }
            sacc[j][0] = v0; sacc[j][1] = v1; sacc[j][2] = v2; sacc[j][3] = v3;
            mx0 = fmaxf(mx0, fmaxf(v0, v1));
            mx1 = fmaxf(mx1, fmaxf(v2, v3));
        }
        mx0 = fmaxf(mx0, __shfl_xor_sync(0xffffffffu, mx0, 1));
        mx0 = fmaxf(mx0, __shfl_xor_sync(0xffffffffu, mx0, 2));
        mx1 = fmaxf(mx1, __shfl_xor_sync(0xffffffffu, mx1, 1));
        mx1 = fmaxf(mx1, __shfl_xor_sync(0xffffffffu, mx1, 2));
        float mn0 = fmaxf(m0, mx0), mn1 = fmaxf(m1, mx1);
        float c0 = exp2f(m0 - mn0), c1 = exp2f(m1 - mn1);
        float rs0 = 0.0f, rs1 = 0.0f;
#pragma unroll
        for (int j = 0; j < 8; j++) {
            float p0 = exp2f(sacc[j][0] - mn0);
            float p1 = exp2f(sacc[j][1] - mn0);
            float p2 = exp2f(sacc[j][2] - mn1);
            float p3 = exp2f(sacc[j][3] - mn1);
            sacc[j][0] = p0; sacc[j][1] = p1; sacc[j][2] = p2; sacc[j][3] = p3;
            rs0 += p0 + p1;
            rs1 += p2 + p3;
        }
        rs0 += __shfl_xor_sync(0xffffffffu, rs0, 1);
        rs0 += __shfl_xor_sync(0xffffffffu, rs0, 2);
        rs1 += __shfl_xor_sync(0xffffffffu, rs1, 1);
        rs1 += __shfl_xor_sync(0xffffffffu, rs1, 2);
        l0 = l0 * c0 + rs0;
        l1 = l1 * c1 + rs1;
        m0 = mn0; m1 = mn1;
#pragma unroll
        for (int e = 0; e < 8; e++) {
            oacc[e][0] *= c0; oacc[e][1] *= c0;
            oacc[e][2] *= c1; oacc[e][3] *= c1;
        }

        // ---- O += P @ V (3-pass, d-tile pairs, pass-major) ----
#pragma unroll
        for (int kt = 0; kt < 4; kt++) {
            uint32_t ph[4], pl[4];
            split_pack2(sacc[2 * kt][0],     sacc[2 * kt][1],     ph[0], pl[0]);
            split_pack2(sacc[2 * kt][2],     sacc[2 * kt][3],     ph[1], pl[1]);
            split_pack2(sacc[2 * kt + 1][0], sacc[2 * kt + 1][1], ph[2], pl[2]);
            split_pack2(sacc[2 * kt + 1][2], sacc[2 * kt + 1][3], ph[3], pl[3]);
#pragma unroll
            for (int ep = 0; ep < 2; ep++) {
                const int e0 = 2 * ep, e1 = 2 * ep + 1;
                uint32_t vh0[4], vl0[4], vh1[4], vl1[4];
                uint32_t o0 = (uint32_t)((kt * 16 + vrow) * A2_RS) + vcol + e0 * 32;
                uint32_t o1 = (uint32_t)((kt * 16 + vrow) * A2_RS) + vcol + e1 * 32;
                ldsm4t(vh0, VH + o0);
                ldsm4t(vl0, VL + o0);
                ldsm4t(vh1, VH + o1);
                ldsm4t(vl1, VL + o1);
                mma_bf16(oacc[2 * e0],     ph, vh0[0], vh0[1]);
                mma_bf16(oacc[2 * e0 + 1], ph, vh0[2], vh0[3]);
                mma_bf16(oacc[2 * e1],     ph, vh1[0], vh1[1]);
                mma_bf16(oacc[2 * e1 + 1], ph, vh1[2], vh1[3]);
                mma_bf16(oacc[2 * e0],     ph, vl0[0], vl0[1]);
                mma_bf16(oacc[2 * e0 + 1], ph, vl0[2], vl0[3]);
                mma_bf16(oacc[2 * e1],     ph, vl1[0], vl1[1]);
                mma_bf16(oacc[2 * e1 + 1], ph, vl1[2], vl1[3]);
                mma_bf16(oacc[2 * e0],     pl, vh0[0], vh0[1]);
                mma_bf16(oacc[2 * e0 + 1], pl, vh0[2], vh0[3]);
                mma_bf16(oacc[2 * e1],     pl, vh1[0], vh1[1]);
                mma_bf16(oacc[2 * e1 + 1], pl, vh1[2], vh1[3]);
            }
        }

        // drain in-flight cp.async group before buffer reuse
        cp_wait<0>();
        __syncthreads();
    }

    // ---- epilogue: normalize, split, write yh/yl ----
    const float i0 = 1.0f / l0, i1 = 1.0f / l1;
    const size_t row0 = (size_t)b * Tv + qb * 64 + wq + r0;
#pragma unroll
    for (int e = 0; e < 8; e++) {
        uint32_t h01, l01, h23, l23;
        split_pack2(oacc[e][0] * i0, oacc[e][1] * i0, h01, l01);
        split_pack2(oacc[e][2] * i1, oacc[e][3] * i1, h23, l23);
        size_t o0 = (row0 * Cv + coff + e * 8 + cpair) >> 1;
        size_t o1 = ((row0 + 8) * Cv + coff + e * 8 + cpair) >> 1;
        ((uint32_t*)yh)[o0] = h01;
        ((uint32_t*)yl)[o0] = l01;
        ((uint32_t*)yh)[o1] = h23;
        ((uint32_t*)yl)[o1] = l23;
    }
}

// ---------------------------------------------------------------------------
extern "C" void kernel_launch(void* const* d_in, const int* in_sizes, int n_in,
                              void* d_out, int out_size)
{
    const float* x      = (const float*)d_in[0];   // [4,2048,1024]
    const float* w_attn = (const float*)d_in[1];   // [1024,3072]
    const float* w_proj = (const float*)d_in[2];   // [1024,1024]
    float* out = (float*)d_out;                    // [4,2048,1024]

    void *p_qh, *p_ql, *p_xh, *p_xl, *p_yh, *p_yl, *p_wah, *p_wal, *p_wph, *p_wpl;
    cudaGetSymbolAddress(&p_qh, g_qkvh);
    cudaGetSymbolAddress(&p_ql, g_qkvl);
    cudaGetSymbolAddress(&p_xh, g_xh);
    cudaGetSymbolAddress(&p_xl, g_xl);
    cudaGetSymbolAddress(&p_yh, g_yh);
    cudaGetSymbolAddress(&p_yl, g_yl);
    cudaGetSymbolAddress(&p_wah, g_wah);
    cudaGetSymbolAddress(&p_wal, g_wal);
    cudaGetSymbolAddress(&p_wph, g_wph);
    cudaGetSymbolAddress(&p_wpl, g_wpl);

    cudaFuncSetAttribute(gemm_hmma_kernel<true>,
                         cudaFuncAttributeMaxDynamicSharedMemorySize, GH_SMEM);
    cudaFuncSetAttribute(gemm_hmma_kernel<false>,
                         cudaFuncAttributeMaxDynamicSharedMemorySize, GH_SMEM);
    cudaFuncSetAttribute(attn_tc_kernel,
                         cudaFuncAttributeMaxDynamicSharedMemorySize, A2_SMEM);

    // 1. split x into bf16 hi/lo
    split_kernel<<<1024, 256>>>(x, (__nv_bfloat16*)p_xh, (__nv_bfloat16*)p_xl,
                                (size_t)MROWS * Cv / 4);
    // 2. transpose+split weights
    splitT_kernel<<<dim3(NQKV / 32, Cv / 32), 256>>>(
        w_attn, (__nv_bfloat16*)p_wah, (__nv_bfloat16*)p_wal, Cv, NQKV);
    splitT_kernel<<<dim3(Cv / 32, Cv / 32), 256>>>(
        w_proj, (__nv_bfloat16*)p_wph, (__nv_bfloat16*)p_wpl, Cv, Cv);

    // 3. qkv = x @ w_attn -> split bf16 outputs directly
    gemm_hmma_kernel<true><<<dim3(NQKV / 128, MROWS / 128), 128, GH_SMEM>>>(
        (const __nv_bfloat16*)p_xh, (const __nv_bfloat16*)p_xl,
        (const __nv_bfloat16*)p_wah, (const __nv_bfloat16*)p_wal,
        nullptr, (__nv_bfloat16*)p_qh, (__nv_bfloat16*)p_ql,
        MROWS, NQKV, Cv);

    // 4. tensor-core attention -> yh/yl (64-row Q blocks, 2 CTAs/SM)
    attn_tc_kernel<<<dim3(Tv / 64, Bv * Hv), 128, A2_SMEM>>>(
        (const __nv_bfloat16*)p_qh, (const __nv_bfloat16*)p_ql,
        (__nv_bfloat16*)p_yh, (__nv_bfloat16*)p_yl);

    // 5. out = y @ w_proj (fp32 output)
    gemm_hmma_kernel<false><<<dim3(Cv / 128, MROWS / 128), 128, GH_SMEM>>>(
        (const __nv_bfloat16*)p_yh, (const __nv_bfloat16*)p_yl,
        (const __nv_bfloat16*)p_wph, (const __nv_bfloat16*)p_wpl,
        out, nullptr, nullptr, MROWS, Cv, Cv);
}